// round 2
// baseline (speedup 1.0000x reference)
#include <cuda_runtime.h>

#define BATCH   32
#define CIN     64
#define COUT    64
#define HH      64
#define WW      64
#define HOUT    62
#define WOUT    62
#define KTOT    576          // CIN * 3 * 3
#define BLOCK   128
#define XSTRIDE 36           // 32 batches + 4 pad (16B-aligned rows, 4-way STS ok)
#define KCHUNK  32
#define WSTRIDE 33           // 32 kk + 1 pad -> bank = (c + kk) % 32
#define NCHUNK  18           // 576 / 32

#define SMEM_FLOATS (KTOT * XSTRIDE + 2 * COUT * WSTRIDE)   // 20736 + 4224 = 24960
#define SMEM_BYTES  (SMEM_FLOATS * 4)                        // 99840

typedef unsigned long long u64;

__device__ __forceinline__ u64 pk(float lo, float hi) {
    u64 r;
    asm("mov.b64 %0, {%1, %2};" : "=l"(r) : "f"(lo), "f"(hi));
    return r;
}
__device__ __forceinline__ void upk(u64 v, float& lo, float& hi) {
    asm("mov.b64 {%0, %1}, %2;" : "=f"(lo), "=f"(hi) : "l"(v));
}
// Packed dual-FMA: d.lo += a.lo*b.lo ; d.hi += a.hi*b.hi  (Blackwell f32x2 pipe, 2x FFMA rate)
__device__ __forceinline__ void fma2(u64& d, u64 a, u64 b) {
    asm("fma.rn.f32x2 %0, %1, %2, %0;" : "+l"(d) : "l"(a), "l"(b));
}

__global__ void __launch_bounds__(BLOCK)
lc2d_kernel(const float* __restrict__ features,
            const float* __restrict__ weights,
            const float* __restrict__ bias,
            float* __restrict__ out)
{
    extern __shared__ float smem[];
    float* x_s = smem;                       // [KTOT][XSTRIDE]
    float* w_s = smem + KTOT * XSTRIDE;      // [2][COUT][WSTRIDE]

    const int tid = threadIdx.x;
    const int w   = blockIdx.x;
    const int h   = blockIdx.y;

    // compute-phase mapping: c = 2*cg + {0,1}, b = bg*8 + 0..7
    const int cg = tid & 31;     // 0..31
    const int bg = tid >> 5;     // 0..3

    // weight-loader mapping: 512 float4 per 32-k chunk; q = float4 within a c-row
    const int qq    = tid & 7;   // 0..7
    const int cbase = tid >> 3;  // 0..15  (c = cbase + u*16, u = 0..3)

    const float* wloc = weights + (size_t)(h * WOUT + w) * (COUT * KTOT);

    // ---- prefetch weight chunk 0 into registers (LDG in flight during gather) ----
    float4 pre0 = *(const float4*)(wloc + (cbase     ) * KTOT + qq * 4);
    float4 pre1 = *(const float4*)(wloc + (cbase + 16) * KTOT + qq * 4);
    float4 pre2 = *(const float4*)(wloc + (cbase + 32) * KTOT + qq * 4);
    float4 pre3 = *(const float4*)(wloc + (cbase + 48) * KTOT + qq * 4);

    // ---- gather patches into x_s[r][b]  (r = cin*9 + i*3 + j) ----
    // idx order: r fastest (j fastest) -> consecutive threads read ~row-contiguous
    // features; STS bank = (4r + b) % 32 -> 4-way max (one-time cost).
    for (int idx = tid; idx < BATCH * KTOT; idx += BLOCK) {
        int b   = idx / KTOT;
        int r   = idx - b * KTOT;
        int cin = r / 9;
        int f   = r - cin * 9;
        int i   = f / 3;
        int j   = f - i * 3;
        x_s[r * XSTRIDE + b] =
            features[((b * CIN + cin) * HH + (h + i)) * WW + (w + j)];
    }

    // ---- store chunk 0 into w_s buffer 0 (STS.32, conflict-free: bank = c+4q+e) ----
    {
        float* dst = w_s + cbase * WSTRIDE + qq * 4;
        dst[0] = pre0.x; dst[1] = pre0.y; dst[2] = pre0.z; dst[3] = pre0.w;
        dst += 16 * WSTRIDE;
        dst[0] = pre1.x; dst[1] = pre1.y; dst[2] = pre1.z; dst[3] = pre1.w;
        dst += 16 * WSTRIDE;
        dst[0] = pre2.x; dst[1] = pre2.y; dst[2] = pre2.z; dst[3] = pre2.w;
        dst += 16 * WSTRIDE;
        dst[0] = pre3.x; dst[1] = pre3.y; dst[2] = pre3.z; dst[3] = pre3.w;
    }
    __syncthreads();

    u64 acc[4][2];
    #pragma unroll
    for (int p = 0; p < 4; p++) { acc[p][0] = 0ULL; acc[p][1] = 0ULL; }

    int buf = 0;
    for (int ch = 0; ch < NCHUNK; ch++) {
        const bool more = (ch + 1 < NCHUNK);
        if (more) {
            const float* src = wloc + (ch + 1) * KCHUNK;
            pre0 = *(const float4*)(src + (cbase     ) * KTOT + qq * 4);
            pre1 = *(const float4*)(src + (cbase + 16) * KTOT + qq * 4);
            pre2 = *(const float4*)(src + (cbase + 32) * KTOT + qq * 4);
            pre3 = *(const float4*)(src + (cbase + 48) * KTOT + qq * 4);
        }

        const float* wb = w_s + buf * (COUT * WSTRIDE);
        const float* xb = x_s + ch * KCHUNK * XSTRIDE + bg * 8;

        #pragma unroll
        for (int kk = 0; kk < KCHUNK; kk++) {
            // 8 batches for this thread: two LDS.128 (warp-broadcast, 1 wf each)
            float4 xv0 = *(const float4*)(xb + kk * XSTRIDE);
            float4 xv1 = *(const float4*)(xb + kk * XSTRIDE + 4);
            u64 xp0 = pk(xv0.x, xv0.y);
            u64 xp1 = pk(xv0.z, xv0.w);
            u64 xp2 = pk(xv1.x, xv1.y);
            u64 xp3 = pk(xv1.z, xv1.w);
            // 2 couts: scalar LDS, bank = (c + kk) -> 2-way max
            float w0 = wb[(2 * cg    ) * WSTRIDE + kk];
            float w1 = wb[(2 * cg + 1) * WSTRIDE + kk];
            u64 wp0 = pk(w0, w0);
            u64 wp1 = pk(w1, w1);

            fma2(acc[0][0], xp0, wp0); fma2(acc[1][0], xp1, wp0);
            fma2(acc[2][0], xp2, wp0); fma2(acc[3][0], xp3, wp0);
            fma2(acc[0][1], xp0, wp1); fma2(acc[1][1], xp1, wp1);
            fma2(acc[2][1], xp2, wp1); fma2(acc[3][1], xp3, wp1);
        }

        if (more) {
            // write next chunk into the other buffer; safe with a single barrier:
            // every warp already passed the barrier that followed its own STS of
            // the current chunk, so no warp can still be reading buf^1.
            float* dst = w_s + (buf ^ 1) * (COUT * WSTRIDE) + cbase * WSTRIDE + qq * 4;
            dst[0] = pre0.x; dst[1] = pre0.y; dst[2] = pre0.z; dst[3] = pre0.w;
            dst += 16 * WSTRIDE;
            dst[0] = pre1.x; dst[1] = pre1.y; dst[2] = pre1.z; dst[3] = pre1.w;
            dst += 16 * WSTRIDE;
            dst[0] = pre2.x; dst[1] = pre2.y; dst[2] = pre2.z; dst[3] = pre2.w;
            dst += 16 * WSTRIDE;
            dst[0] = pre3.x; dst[1] = pre3.y; dst[2] = pre3.z; dst[3] = pre3.w;
            __syncthreads();
        }
        buf ^= 1;
    }

    // ---- epilogue: unpack, add bias, scattered STG.32 ----
    const float* bl = bias + (h * WOUT + w) * COUT;
    const float b0v = bl[2 * cg];
    const float b1v = bl[2 * cg + 1];
    const int c0 = 2 * cg;

    #pragma unroll
    for (int p = 0; p < 4; p++) {
        const int bb = bg * 8 + 2 * p;
        float lo, hi;
        upk(acc[p][0], lo, hi);
        out[(( bb      * COUT + c0    ) * HOUT + h) * WOUT + w] = lo + b0v;
        out[(((bb + 1) * COUT + c0    ) * HOUT + h) * WOUT + w] = hi + b0v;
        upk(acc[p][1], lo, hi);
        out[(( bb      * COUT + c0 + 1) * HOUT + h) * WOUT + w] = lo + b1v;
        out[(((bb + 1) * COUT + c0 + 1) * HOUT + h) * WOUT + w] = hi + b1v;
    }
}

extern "C" void kernel_launch(void* const* d_in, const int* in_sizes, int n_in,
                              void* d_out, int out_size)
{
    // robust input identification by element count
    const float* features = nullptr;
    const float* weights  = nullptr;
    const float* bias     = nullptr;
    for (int i = 0; i < n_in; i++) {
        if      (in_sizes[i] == BATCH * CIN * HH * WW)              features = (const float*)d_in[i];
        else if (in_sizes[i] == HOUT * WOUT * COUT * CIN * 9)       weights  = (const float*)d_in[i];
        else if (in_sizes[i] == HOUT * WOUT * COUT)                 bias     = (const float*)d_in[i];
    }
    float* out = (float*)d_out;

    cudaFuncSetAttribute(lc2d_kernel,
                         cudaFuncAttributeMaxDynamicSharedMemorySize, SMEM_BYTES);

    dim3 grid(WOUT, HOUT);
    lc2d_kernel<<<grid, BLOCK, SMEM_BYTES>>>(features, weights, bias, out);
}

// round 3
// speedup vs baseline: 1.0642x; 1.0642x over previous
#include <cuda_runtime.h>
#include <cstdint>

#define BATCH   32
#define CIN     64
#define COUT    64
#define HH      64
#define WW      64
#define HOUT    62
#define WOUT    62
#define KTOT    576          // CIN * 3 * 3
#define BLOCK   128
#define KCHUNK  32
#define XSTRIDE 36           // 32 batches + 4 pad (16B-aligned rows for LDS.128)
#define WSTRIDE 33           // 32 kk + 1 pad -> 2-way max on w reads
#define NCHUNK  18           // 576 / 32

typedef unsigned long long u64;

__device__ __forceinline__ u64 pk(float lo, float hi) {
    u64 r;
    asm("mov.b64 %0, {%1, %2};" : "=l"(r) : "f"(lo), "f"(hi));
    return r;
}
__device__ __forceinline__ void upk(u64 v, float& lo, float& hi) {
    asm("mov.b64 {%0, %1}, %2;" : "=f"(lo), "=f"(hi) : "l"(v));
}
// Packed dual-FMA on the Blackwell f32x2 pipe (2x FFMA rate)
__device__ __forceinline__ void fma2(u64& d, u64 a, u64 b) {
    asm("fma.rn.f32x2 %0, %1, %2, %0;" : "+l"(d) : "l"(a), "l"(b));
}
__device__ __forceinline__ void cp4(uint32_t dst, const float* src) {
    asm volatile("cp.async.ca.shared.global [%0], [%1], 4;" :: "r"(dst), "l"(src) : "memory");
}
__device__ __forceinline__ void cpcommit() {
    asm volatile("cp.async.commit_group;" ::: "memory");
}
__device__ __forceinline__ void cpwait1() {
    asm volatile("cp.async.wait_group 1;" ::: "memory");
}

__global__ void __launch_bounds__(BLOCK)
lc2d_kernel(const float* __restrict__ features,
            const float* __restrict__ weights,
            const float* __restrict__ bias,
            float* __restrict__ out)
{
    // 3-deep x ring (chunked over K) + 2-deep w ping-pong: 30,720 B total
    __shared__ float x_s[3][KCHUNK][XSTRIDE];
    __shared__ float w_s[2][COUT][WSTRIDE];

    const int tid = threadIdx.x;
    const int w   = blockIdx.x;
    const int h   = blockIdx.y;

    // compute mapping: c = 2*cg + {0,1}, b = bg*8 + 0..7
    const int cg = tid & 31;
    const int bg = tid >> 5;
    // w-loader mapping
    const int qq    = tid & 7;
    const int cbase = tid >> 3;
    // x-gather mapping: lane = k-offset within chunk, warp = batch group
    const int rr = tid & 31;
    const int bq = tid >> 5;

    const float* wloc  = weights  + (size_t)(h * WOUT + w) * (COUT * KTOT);
    const float* fbase = features + h * WW + w;

    float4 p0, p1, p2, p3;   // w register relay (one chunk ahead of smem)

    auto ldg_w = [&](int ch) {
        const float* src = wloc + ch * KCHUNK;
        p0 = *(const float4*)(src + (cbase     ) * KTOT + qq * 4);
        p1 = *(const float4*)(src + (cbase + 16) * KTOT + qq * 4);
        p2 = *(const float4*)(src + (cbase + 32) * KTOT + qq * 4);
        p3 = *(const float4*)(src + (cbase + 48) * KTOT + qq * 4);
    };
    auto sts_w = [&](int b) {
        float* dst = &w_s[b][cbase][qq * 4];
        dst[0] = p0.x; dst[1] = p0.y; dst[2] = p0.z; dst[3] = p0.w; dst += 16 * WSTRIDE;
        dst[0] = p1.x; dst[1] = p1.y; dst[2] = p1.z; dst[3] = p1.w; dst += 16 * WSTRIDE;
        dst[0] = p2.x; dst[1] = p2.y; dst[2] = p2.z; dst[3] = p2.w; dst += 16 * WSTRIDE;
        dst[0] = p3.x; dst[1] = p3.y; dst[2] = p3.z; dst[3] = p3.w;
    };
    // gather x chunk ch into ring buffer xb via 4B cp.async (one commit per call)
    auto issue_x = [&](int ch, int xb) {
        int r   = ch * KCHUNK + rr;
        int cin = r / 9;
        int f   = r - cin * 9;
        int i   = f / 3;
        int j   = f - i * 3;
        const float* src = fbase + cin * (HH * WW) + i * WW + j
                         + (size_t)(bq * 8) * (CIN * HH * WW);
        uint32_t dst = (uint32_t)__cvta_generic_to_shared(&x_s[xb][rr][bq * 8]);
        #pragma unroll
        for (int s = 0; s < 8; s++)
            cp4(dst + s * 4, src + (size_t)s * (CIN * HH * WW));
        cpcommit();
    };

    // ---- prologue: w0 -> smem buf0, w1 -> regs; x0, x1 in flight ----
    ldg_w(0);
    issue_x(0, 0);
    issue_x(1, 1);
    sts_w(0);
    ldg_w(1);

    u64 acc[4][2];
    #pragma unroll
    for (int p = 0; p < 4; p++) { acc[p][0] = 0ULL; acc[p][1] = 0ULL; }

    int xc = 0;  // ring index of the chunk being computed
    #pragma unroll 1
    for (int ch = 0; ch < NCHUNK; ch++) {
        // exactly one group committed per iter (prologue committed 2) =>
        // wait_group 1 leaves only the newest group (x(ch+1) or empty) pending,
        // so x(ch) is guaranteed complete here.
        cpwait1();
        __syncthreads();   // publish x(ch), w(ch); ring slot (ch+2)%3 now free

        if (ch + 1 < NCHUNK) sts_w((ch + 1) & 1);   // w(ch+1) regs -> other buf
        if (ch + 2 < NCHUNK) {
            ldg_w(ch + 2);
            int xn = xc + 2; if (xn >= 3) xn -= 3;
            issue_x(ch + 2, xn);                     // commits its group
        } else {
            cpcommit();                              // empty group keeps count
        }

        const float* wb = &w_s[ch & 1][0][0];
        const float* xb = &x_s[xc][0][bg * 8];

        #pragma unroll
        for (int kk = 0; kk < KCHUNK; kk++) {
            float4 xv0 = *(const float4*)(xb + kk * XSTRIDE);       // broadcast
            float4 xv1 = *(const float4*)(xb + kk * XSTRIDE + 4);   // broadcast
            u64 xp0 = pk(xv0.x, xv0.y);
            u64 xp1 = pk(xv0.z, xv0.w);
            u64 xp2 = pk(xv1.x, xv1.y);
            u64 xp3 = pk(xv1.z, xv1.w);
            float w0 = wb[(2 * cg    ) * WSTRIDE + kk];             // 2-way max
            float w1 = wb[(2 * cg + 1) * WSTRIDE + kk];
            u64 wp0 = pk(w0, w0);
            u64 wp1 = pk(w1, w1);

            fma2(acc[0][0], xp0, wp0); fma2(acc[1][0], xp1, wp0);
            fma2(acc[2][0], xp2, wp0); fma2(acc[3][0], xp3, wp0);
            fma2(acc[0][1], xp0, wp1); fma2(acc[1][1], xp1, wp1);
            fma2(acc[2][1], xp2, wp1); fma2(acc[3][1], xp3, wp1);
        }

        xc++; if (xc >= 3) xc -= 3;
    }

    // ---- epilogue: unpack, add bias, scattered STG.32 ----
    const float* bl = bias + (h * WOUT + w) * COUT;
    const float b0v = bl[2 * cg];
    const float b1v = bl[2 * cg + 1];
    const int c0 = 2 * cg;

    #pragma unroll
    for (int p = 0; p < 4; p++) {
        const int bb = bg * 8 + 2 * p;
        float lo, hi;
        upk(acc[p][0], lo, hi);
        out[(( bb      * COUT + c0    ) * HOUT + h) * WOUT + w] = lo + b0v;
        out[(((bb + 1) * COUT + c0    ) * HOUT + h) * WOUT + w] = hi + b0v;
        upk(acc[p][1], lo, hi);
        out[(( bb      * COUT + c0 + 1) * HOUT + h) * WOUT + w] = lo + b1v;
        out[(((bb + 1) * COUT + c0 + 1) * HOUT + h) * WOUT + w] = hi + b1v;
    }
}

extern "C" void kernel_launch(void* const* d_in, const int* in_sizes, int n_in,
                              void* d_out, int out_size)
{
    const float* features = nullptr;
    const float* weights  = nullptr;
    const float* bias     = nullptr;
    for (int i = 0; i < n_in; i++) {
        if      (in_sizes[i] == BATCH * CIN * HH * WW)        features = (const float*)d_in[i];
        else if (in_sizes[i] == HOUT * WOUT * COUT * CIN * 9) weights  = (const float*)d_in[i];
        else if (in_sizes[i] == HOUT * WOUT * COUT)           bias     = (const float*)d_in[i];
    }
    float* out = (float*)d_out;

    dim3 grid(WOUT, HOUT);
    lc2d_kernel<<<grid, BLOCK>>>(features, weights, bias, out);
}